// round 16
// baseline (speedup 1.0000x reference)
#include <cuda_runtime.h>
#include <cuda_fp16.h>
#include <cstdint>

#define SEG 4194304
#define SCALE_Q 0.125f

// ---------------- scratch (__device__ globals; no allocations) ----------------
__device__ __align__(256) __half g_xh[4096*2048], g_xl[4096*2048];
__device__ __align__(256) __half g_wh[6144*2048];
__device__ __align__(256) __half g_owh[2048*2048];
__device__ __align__(256) float g_c1[(size_t)4096*6144];
__device__ __align__(256) __half g_qh[64*1024*128], g_ql[64*1024*128];
__device__ __align__(256) __half g_kh[64*1024*128];
__device__ __align__(256) __half g_vth[64*128*1024];
__device__ __align__(256) __half g_awh[(size_t)64*1024*1024];
__device__ __align__(256) __half g_awl[(size_t)64*1024*1024];
__device__ __align__(256) __half g_a2h[4096*2048], g_a2l[4096*2048];
__device__ float g_vsum[64*128];
__device__ float g_minmax[2];
__device__ float g_ms[2];

// ---------------- helpers ----------------
__device__ __forceinline__ uint32_t s2u(const void* p) {
    uint32_t a;
    asm("{ .reg .u64 t; cvta.to.shared.u64 t, %1; cvt.u32.u64 %0, t; }" : "=r"(a) : "l"(p));
    return a;
}
__device__ __forceinline__ void cpa16(uint32_t d, const void* s) {
    asm volatile("cp.async.cg.shared.global [%0], [%1], 16;" :: "r"(d), "l"(s));
}
#define CP_COMMIT() asm volatile("cp.async.commit_group;")
#define CP_WAIT(n)  asm volatile("cp.async.wait_group %0;" :: "n"(n))

#define LDM4(r0, r1, r2, r3, a) \
    asm volatile("ldmatrix.sync.aligned.m8n8.x4.shared.b16 {%0,%1,%2,%3}, [%4];" \
                 : "=r"(r0), "=r"(r1), "=r"(r2), "=r"(r3) : "r"(a))

#define MMA16816(c, a, b) \
    asm volatile("mma.sync.aligned.m16n8k16.row.col.f32.f16.f16.f32 " \
                 "{%0,%1,%2,%3}, {%4,%5,%6,%7}, {%8,%9}, {%0,%1,%2,%3};" \
                 : "+f"((c)[0]), "+f"((c)[1]), "+f"((c)[2]), "+f"((c)[3]) \
                 : "r"((a)[0]), "r"((a)[1]), "r"((a)[2]), "r"((a)[3]), \
                   "r"((b)[0]), "r"((b)[1]))

__device__ __forceinline__ uint32_t pkh(__half a, __half b) {
    __half2 t = __halves2half2(a, b);
    return *reinterpret_cast<uint32_t*>(&t);
}
__device__ __forceinline__ uint32_t pkh2f(float a, float b) {
    return pkh(__float2half(a), __float2half(b));
}
__device__ __forceinline__ float2 upkh(uint32_t u) {
    __half2 t = *reinterpret_cast<__half2*>(&u);
    return __half22float2(t);
}
// hi/lo fp16 split, pair store
__device__ __forceinline__ void hsplit2(__half* H, __half* L, size_t i, float a, float b) {
    __half ha = __float2half(a), hb = __float2half(b);
    *(uint32_t*)(H + i) = pkh(ha, hb);
    *(uint32_t*)(L + i) = pkh(__float2half(a - __half2float(ha)),
                              __float2half(b - __half2float(hb)));
}
// 8-wide hi/lo split
__device__ __forceinline__ void hsplit8(__half* H, __half* L, size_t i, float4 v0, float4 v1) {
    __half h0 = __float2half(v0.x), h1 = __float2half(v0.y),
           h2 = __float2half(v0.z), h3 = __float2half(v0.w),
           h4 = __float2half(v1.x), h5 = __float2half(v1.y),
           h6 = __float2half(v1.z), h7 = __float2half(v1.w);
    *(uint4*)(H + i) = make_uint4(pkh(h0, h1), pkh(h2, h3), pkh(h4, h5), pkh(h6, h7));
    *(uint4*)(L + i) = make_uint4(
        pkh(__float2half(v0.x - __half2float(h0)), __float2half(v0.y - __half2float(h1))),
        pkh(__float2half(v0.z - __half2float(h2)), __float2half(v0.w - __half2float(h3))),
        pkh(__float2half(v1.x - __half2float(h4)), __float2half(v1.y - __half2float(h5))),
        pkh(__float2half(v1.z - __half2float(h6)), __float2half(v1.w - __half2float(h7))));
}
// 8-wide hi-only pack
__device__ __forceinline__ void hpack8(__half* H, size_t i, float4 v0, float4 v1) {
    *(uint4*)(H + i) = make_uint4(pkh2f(v0.x, v0.y), pkh2f(v0.z, v0.w),
                                  pkh2f(v1.x, v1.y), pkh2f(v1.z, v1.w));
}
__device__ __forceinline__ void atomicMinF(float* addr, float val) {
    int old = __float_as_int(*addr);
    while (val < __int_as_float(old)) {
        int assumed = old;
        old = atomicCAS((int*)addr, assumed, __float_as_int(val));
        if (old == assumed) break;
    }
}
__device__ __forceinline__ void atomicMaxF(float* addr, float val) {
    int old = __float_as_int(*addr);
    while (val > __int_as_float(old)) {
        int assumed = old;
        old = atomicCAS((int*)addr, assumed, __float_as_int(val));
        if (old == assumed) break;
    }
}

__global__ void k_init() {
    g_minmax[0] = __int_as_float(0x7f800000);
    g_minmax[1] = __int_as_float(0xff800000);
}
__global__ void k_scale() {
    float mn = g_minmax[0], mx = g_minmax[1];
    g_ms[0] = mn;
    g_ms[1] = 1.0f / (mx - mn);
}

// ---------------- prep kernels ----------------
__global__ void k_prep_x(const float* __restrict__ xr, const float* __restrict__ xi) {
    size_t i8 = ((size_t)blockIdx.x * 256 + threadIdx.x) * 8;   // 4096*2048
    int m = (int)(i8 >> 11), k = (int)(i8 & 2047);
    const float* src = (k < 1024) ? (xr + (size_t)m * 1024 + k) : (xi + (size_t)m * 1024 + k - 1024);
    float4 v0 = *(const float4*)(src);
    float4 v1 = *(const float4*)(src + 4);
    hsplit8(g_xh, g_xl, i8, v0, v1);
}
__global__ void k_prep_w(const float* __restrict__ wr, const float* __restrict__ wi) {
    size_t i8 = ((size_t)blockIdx.x * 256 + threadIdx.x) * 8;   // 6144*2048
    int p = (int)(i8 >> 11), k = (int)(i8 & 2047);
    int n = p >> 1;
    float4 v0, v1;
    if (!(p & 1)) {
        if (k < 1024) {
            v0 = *(const float4*)(wr + (size_t)n * 1024 + k);
            v1 = *(const float4*)(wr + (size_t)n * 1024 + k + 4);
        } else {
            v0 = *(const float4*)(wi + (size_t)n * 1024 + k - 1024);
            v1 = *(const float4*)(wi + (size_t)n * 1024 + k - 1020);
            v0.x = -v0.x; v0.y = -v0.y; v0.z = -v0.z; v0.w = -v0.w;
            v1.x = -v1.x; v1.y = -v1.y; v1.z = -v1.z; v1.w = -v1.w;
        }
    } else {
        const float* src = (k < 1024) ? (wi + (size_t)n * 1024 + k) : (wr + (size_t)n * 1024 + k - 1024);
        v0 = *(const float4*)(src);
        v1 = *(const float4*)(src + 4);
    }
    hpack8(g_wh, i8, v0, v1);
}
__global__ void k_prep_ow(const float* __restrict__ owr, const float* __restrict__ owi) {
    size_t i8 = ((size_t)blockIdx.x * 256 + threadIdx.x) * 8;   // 2048*2048
    int p = (int)(i8 >> 11), k = (int)(i8 & 2047);
    int n = p >> 1;
    float4 v0, v1;
    if (!(p & 1)) {
        if (k < 1024) {
            v0 = *(const float4*)(owr + (size_t)n * 1024 + k);
            v1 = *(const float4*)(owr + (size_t)n * 1024 + k + 4);
        } else {
            v0 = *(const float4*)(owi + (size_t)n * 1024 + k - 1024);
            v1 = *(const float4*)(owi + (size_t)n * 1024 + k - 1020);
            v0.x = -v0.x; v0.y = -v0.y; v0.z = -v0.z; v0.w = -v0.w;
            v1.x = -v1.x; v1.y = -v1.y; v1.z = -v1.z; v1.w = -v1.w;
        }
    } else {
        const float* src = (k < 1024) ? (owi + (size_t)n * 1024 + k) : (owr + (size_t)n * 1024 + k - 1024);
        v0 = *(const float4*)(src);
        v1 = *(const float4*)(src + 4);
    }
    hpack8(g_owh, i8, v0, v1);
}

// ---------------- transforms ----------------
__global__ void k_trans_qk(const float* __restrict__ br, const float* __restrict__ bi) {
    int idx = blockIdx.x * 256 + threadIdx.x;   // 64*1024*32
    int hd2 = (idx & 31) * 2, t = (idx >> 5) & 1023, bh = idx >> 15;
    int b = bh >> 4, h = bh & 15;
    size_t m = (size_t)t * 4 + b;
    int nq = h * 64 + hd2;
    const float* cr = g_c1 + m * 6144;
    float4 q = *(const float4*)(cr + 2 * nq);
    float4 kv = *(const float4*)(cr + 2 * nq + 2048);
    float qr0 = q.x + br[nq],     qi0 = q.y + bi[nq];
    float qr1 = q.z + br[nq + 1], qi1 = q.w + bi[nq + 1];
    float kr0 = kv.x + br[nq + 1024], ki0 = kv.y + bi[nq + 1024];
    float kr1 = kv.z + br[nq + 1025], ki1 = kv.w + bi[nq + 1025];
    size_t base = ((size_t)bh * 1024 + t) * 128;
    hsplit2(g_qh, g_ql, base + hd2,      qr0 * SCALE_Q, qr1 * SCALE_Q);
    hsplit2(g_qh, g_ql, base + 64 + hd2, qi0 * SCALE_Q, qi1 * SCALE_Q);
    *(uint32_t*)(g_kh + base + hd2)      = pkh2f(kr0 + ki0, kr1 + ki1);
    *(uint32_t*)(g_kh + base + 64 + hd2) = pkh2f(kr0 - ki0, kr1 - ki1);
}

__global__ void k_trans_v(const float* __restrict__ br, const float* __restrict__ bi) {
    __shared__ float sv[64][129];
    int bh = blockIdx.y, tblk = blockIdx.x;
    int b = bh >> 4, h = bh & 15;
    for (int i = threadIdx.x; i < 8192; i += 256) {
        int tl = i >> 7, n = i & 127;
        int hd = n & 63;
        int im = (n >= 64);
        size_t m = (size_t)(tblk * 64 + tl) * 4 + b;
        int nv = 2048 + h * 64 + hd;
        sv[tl][n] = g_c1[m * 6144 + 2 * nv + im] + (im ? bi[nv] : br[nv]);
    }
    __syncthreads();
    for (int i = threadIdx.x; i < 4096; i += 256) {
        int n = i >> 5, tl2 = (i & 31) * 2;
        size_t o = ((size_t)bh * 128 + n) * 1024 + tblk * 64 + tl2;
        *(uint32_t*)(g_vth + o) = pkh2f(sv[tl2][n], sv[tl2 + 1][n]);
    }
}

// per-head V column sums over the SAME fp16 values the MMA consumes
__global__ void k_vsum() {
    int bh = blockIdx.x, n = threadIdx.x;
    const __half* ph = g_vth + ((size_t)bh * 128 + n) * 1024;
    float s = 0.f;
    for (int t = 0; t < 1024; t += 2) {
        float2 a = upkh(*(const uint32_t*)(ph + t));
        s += a.x + a.y;
    }
    g_vsum[bh * 128 + n] = s;
}

__global__ void k_avg(float* __restrict__ out) {
    size_t i4 = ((size_t)blockIdx.x * 256 + threadIdx.x) * 4;   // 4Mi outputs
    int b = (int)(i4 >> 20);
    size_t qk = i4 & 0xFFFFFu;
    float s0 = 0.f, s1 = 0.f, s2 = 0.f, s3 = 0.f;
    #pragma unroll
    for (int h = 0; h < 16; h++) {
        size_t o = (((size_t)(b * 16 + h)) << 20) + qk;
        uint2 uh = *(const uint2*)(g_awh + o);
        uint2 ul = *(const uint2*)(g_awl + o);
        float2 a0 = upkh(uh.x), a1 = upkh(uh.y), b0 = upkh(ul.x), b1 = upkh(ul.y);
        s0 += a0.x + b0.x; s1 += a0.y + b0.y;
        s2 += a1.x + b1.x; s3 += a1.y + b1.y;
    }
    float mn = g_ms[0], sc = g_ms[1];
    float4 r;
    r.x = (s0 * 0.0625f - mn) * sc; r.y = (s1 * 0.0625f - mn) * sc;
    r.z = (s2 * 0.0625f - mn) * sc; r.w = (s3 * 0.0625f - mn) * sc;
    *(float4*)(out + i4) = r;
}

// ---------------- HMMA GEMM (fp16 2-product: A hi/lo x B hi) ----------------
// SMEM per stage: A_h 8KB | A_l 8KB | B_h 8KB = 24KB; double buffered = 48KB.
// MODE 0: proj  A=g_x     B=g_w   C=g_c1               K=2048
// MODE 1: qk    A=g_q     B=g_k   C=awh/awl + minmax   K=128,  z=head
// MODE 2: av    A=awh/awl B=g_vt  C=a2h/a2l (affine)   K=1024, z=head
// MODE 3: oproj A=g_a2    B=g_ow  C=out re/im+bias     K=2048
template<int MODE>
__global__ __launch_bounds__(256, 2) void k_gemm(
    const float* __restrict__ biasR, const float* __restrict__ biasI,
    float* __restrict__ outR, float* __restrict__ outI)
{
    extern __shared__ char sm[];
    const int tid = threadIdx.x, lane = tid & 31, wid = tid >> 5;
    const int wm = wid >> 2, wn = wid & 3;
    const int bm = blockIdx.y * 128, bn = blockIdx.x * 128, z = blockIdx.z;

    constexpr int ld = (MODE == 1) ? 128 : (MODE == 2) ? 1024 : 2048;
    constexpr int nk = (MODE == 1) ? 4 : (MODE == 2) ? 32 : 64;
    constexpr int STG = 24576;

    const __half *Ah, *Al, *Bh;
    if (MODE == 0)      { Ah = g_xh;  Al = g_xl;  Bh = g_wh; }
    else if (MODE == 1) {
        Ah = g_qh + (size_t)z * 131072; Al = g_ql + (size_t)z * 131072;
        Bh = g_kh + (size_t)z * 131072;
    } else if (MODE == 2) {
        Ah = g_awh + ((size_t)z << 20); Al = g_awl + ((size_t)z << 20);
        Bh = g_vth + (size_t)z * 131072;
    } else              { Ah = g_a2h; Al = g_a2l; Bh = g_owh; }

    const uint32_t sb = s2u(sm);
    float acc[4][4][4] = {};

    const int srow = tid >> 1, sc0 = (tid & 1) * 2;
    const int ra  = (lane & 7) + ((lane >> 3) & 1) * 8;
    const int ksa = lane >> 4;
    const int rb  = wn * 32 + ((lane >> 4) & 1) * 8 + (lane & 7);
    const int ksb = (lane >> 3) & 1;

    // ---- prologue: stage 0 ----
    {
        const __half* srcs[3] = {Ah, Al, Bh};
        const int rbase[3] = {bm, bm, bn};
        #pragma unroll
        for (int o = 0; o < 3; o++) {
            size_t g = (size_t)(rbase[o] + srow) * ld;
            uint32_t db = sb + o * 8192 + srow * 64;
            #pragma unroll
            for (int u = 0; u < 2; u++) {
                int c = sc0 + u;
                cpa16(db + ((c ^ ((srow >> 1) & 3)) << 4), srcs[o] + g + c * 8);
            }
        }
        CP_COMMIT();
    }

    for (int kt = 0; kt < nk; kt++) {
        if (kt + 1 < nk) {
            const int k0 = (kt + 1) * 32;
            const int buf = (kt + 1) & 1;
            const __half* srcs[3] = {Ah, Al, Bh};
            const int rbase[3] = {bm, bm, bn};
            #pragma unroll
            for (int o = 0; o < 3; o++) {
                size_t g = (size_t)(rbase[o] + srow) * ld + k0;
                uint32_t db = sb + buf * STG + o * 8192 + srow * 64;
                #pragma unroll
                for (int u = 0; u < 2; u++) {
                    int c = sc0 + u;
                    cpa16(db + ((c ^ ((srow >> 1) & 3)) << 4), srcs[o] + g + c * 8);
                }
            }
            CP_COMMIT();
            CP_WAIT(1);
        } else {
            CP_WAIT(0);
        }
        __syncthreads();

        // ---- compute on buffer kt&1 ----
        {
            const uint32_t base = sb + (kt & 1) * STG;
            #pragma unroll
            for (int kk = 0; kk < 2; kk++) {
                uint32_t bH[4][2];
                #pragma unroll
                for (int jj = 0; jj < 2; jj++) {
                    int row = rb + jj * 16;
                    int seg = kk * 2 + ksb;
                    uint32_t off = row * 64 + ((seg ^ ((row >> 1) & 3)) << 4);
                    LDM4(bH[2*jj][0], bH[2*jj][1], bH[2*jj+1][0], bH[2*jj+1][1], base + 16384 + off);
                }
                #pragma unroll
                for (int i = 0; i < 4; i++) {
                    uint32_t aH[4], aL[4];
                    int row = wm * 64 + i * 16 + ra;
                    int seg = kk * 2 + ksa;
                    uint32_t off = row * 64 + ((seg ^ ((row >> 1) & 3)) << 4);
                    LDM4(aH[0], aH[1], aH[2], aH[3], base + off);
                    LDM4(aL[0], aL[1], aL[2], aL[3], base + 8192 + off);
                    #pragma unroll
                    for (int j = 0; j < 4; j++) {
                        MMA16816(acc[i][j], aH, bH[j]);
                        MMA16816(acc[i][j], aL, bH[j]);
                    }
                }
            }
        }
        __syncthreads();
    }

    // ---------------- epilogue ----------------
    float lmn = __int_as_float(0x7f800000), lmx = __int_as_float(0xff800000);
    float scv = 0.f, mnsc = 0.f;
    if (MODE == 2) { scv = g_ms[1]; mnsc = g_ms[0] * scv; }

    #pragma unroll
    for (int i = 0; i < 4; i++) {
        const int r0 = bm + wm * 64 + i * 16 + (lane >> 2);
        #pragma unroll
        for (int j = 0; j < 4; j++) {
            const float* c = acc[i][j];
            const int n0 = wn * 32 + j * 8 + (lane & 3) * 2;
            if (MODE == 0) {
                *(float2*)(g_c1 + (size_t)r0 * 6144 + bn + n0)       = make_float2(c[0], c[1]);
                *(float2*)(g_c1 + (size_t)(r0 + 8) * 6144 + bn + n0) = make_float2(c[2], c[3]);
            } else if (MODE == 1) {
                __half* AH = g_awh + ((size_t)z << 20);
                __half* AL = g_awl + ((size_t)z << 20);
                hsplit2(AH, AL, (size_t)r0 * 1024 + bn + n0, c[0], c[1]);
                hsplit2(AH, AL, (size_t)(r0 + 8) * 1024 + bn + n0, c[2], c[3]);
                lmn = fminf(lmn, fminf(fminf(c[0], c[1]), fminf(c[2], c[3])));
                lmx = fmaxf(lmx, fmaxf(fmaxf(c[0], c[1]), fmaxf(c[2], c[3])));
            } else if (MODE == 2) {
                const int b = z >> 4, h = z & 15;
                const float* S = g_vsum + z * 128;
                float v00 = scv * c[0] - mnsc * S[n0];
                float v01 = scv * c[1] - mnsc * S[n0 + 1];
                float v10 = scv * c[2] - mnsc * S[n0];
                float v11 = scv * c[3] - mnsc * S[n0 + 1];
                size_t e = (n0 < 64) ? (size_t)(h * 64 + n0) : (size_t)(1024 + h * 64 + n0 - 64);
                hsplit2(g_a2h, g_a2l, ((size_t)r0 * 4 + b) * 2048 + e, v00, v01);
                hsplit2(g_a2h, g_a2l, ((size_t)(r0 + 8) * 4 + b) * 2048 + e, v10, v11);
            } else {
                const int nc = ((bn + n0) >> 1);
                outR[(size_t)r0 * 1024 + nc]       = c[0] + biasR[nc];
                outI[(size_t)r0 * 1024 + nc]       = c[1] + biasI[nc];
                outR[(size_t)(r0 + 8) * 1024 + nc] = c[2] + biasR[nc];
                outI[(size_t)(r0 + 8) * 1024 + nc] = c[3] + biasI[nc];
            }
        }
    }
    if (MODE == 1) {
        #pragma unroll
        for (int off = 16; off; off >>= 1) {
            lmn = fminf(lmn, __shfl_xor_sync(0xffffffffu, lmn, off));
            lmx = fmaxf(lmx, __shfl_xor_sync(0xffffffffu, lmx, off));
        }
        float* red = (float*)sm;
        if (lane == 0) { red[wid] = lmn; red[8 + wid] = lmx; }
        __syncthreads();
        if (tid == 0) {
            float mn = red[0], mx = red[8];
            #pragma unroll
            for (int w = 1; w < 8; w++) { mn = fminf(mn, red[w]); mx = fmaxf(mx, red[8 + w]); }
            atomicMinF(&g_minmax[0], mn);
            atomicMaxF(&g_minmax[1], mx);
        }
    }
}

// ---------------- launch ----------------
extern "C" void kernel_launch(void* const* d_in, const int* in_sizes, int n_in,
                              void* d_out, int out_size)
{
    const float* xr  = (const float*)d_in[0];
    const float* xi  = (const float*)d_in[1];
    const float* wr  = (const float*)d_in[2];
    const float* wi  = (const float*)d_in[3];
    const float* br  = (const float*)d_in[4];
    const float* bi  = (const float*)d_in[5];
    const float* owr = (const float*)d_in[6];
    const float* owi = (const float*)d_in[7];
    const float* obr = (const float*)d_in[8];
    const float* obi = (const float*)d_in[9];
    float* out = (float*)d_out;

    const int SMEM = 49152;
    cudaFuncSetAttribute(k_gemm<0>, cudaFuncAttributeMaxDynamicSharedMemorySize, SMEM);
    cudaFuncSetAttribute(k_gemm<1>, cudaFuncAttributeMaxDynamicSharedMemorySize, SMEM);
    cudaFuncSetAttribute(k_gemm<2>, cudaFuncAttributeMaxDynamicSharedMemorySize, SMEM);
    cudaFuncSetAttribute(k_gemm<3>, cudaFuncAttributeMaxDynamicSharedMemorySize, SMEM);

    k_init<<<1, 1>>>();
    k_prep_x<<<4096, 256>>>(xr, xi);
    k_prep_w<<<6144, 256>>>(wr, wi);
    k_prep_ow<<<2048, 256>>>(owr, owi);

    k_gemm<0><<<dim3(48, 32), 256, SMEM>>>(nullptr, nullptr, nullptr, nullptr);
    k_trans_qk<<<8192, 256>>>(br, bi);
    k_trans_v<<<dim3(16, 64), 256>>>(br, bi);
    k_vsum<<<64, 128>>>();

    k_gemm<1><<<dim3(8, 8, 64), 256, SMEM>>>(nullptr, nullptr, nullptr, nullptr);
    k_scale<<<1, 1>>>();

    k_gemm<2><<<dim3(1, 8, 64), 256, SMEM>>>(nullptr, nullptr, nullptr, nullptr);
    k_avg<<<4096, 256>>>(out + 2 * (size_t)SEG);

    k_gemm<3><<<dim3(16, 32), 256, SMEM>>>(obr, obi, out, out + SEG);
}

// round 17
// speedup vs baseline: 1.1648x; 1.1648x over previous
#include <cuda_runtime.h>
#include <cuda_bf16.h>
#include <cstdint>

#define SEG 4194304
#define SCALE_Q 0.125f

// ---------------- scratch (__device__ globals; no allocations) ----------------
__device__ __align__(256) __nv_bfloat16 g_xh[4096*2048], g_xl[4096*2048];
__device__ __align__(256) __nv_bfloat16 g_wh[6144*2048], g_wl[6144*2048];
__device__ __align__(256) __nv_bfloat16 g_owh[2048*2048], g_owl[2048*2048];
__device__ __align__(256) float g_c1[(size_t)4096*6144];
__device__ __align__(256) __nv_bfloat16 g_qh[64*1024*128], g_ql[64*1024*128];
__device__ __align__(256) __nv_bfloat16 g_kh[64*1024*128], g_kl[64*1024*128];
__device__ __align__(256) __nv_bfloat16 g_vth[64*128*1024], g_vtl[64*128*1024];
__device__ __align__(256) __nv_bfloat16 g_awh[(size_t)64*1024*1024];
__device__ __align__(256) __nv_bfloat16 g_awl[(size_t)64*1024*1024];
__device__ __align__(256) __nv_bfloat16 g_a2h[4096*2048], g_a2l[4096*2048];
__device__ float g_vsum[64*128];
__device__ float g_minmax[2];
__device__ float g_ms[2];

// ---------------- helpers ----------------
__device__ __forceinline__ uint32_t s2u(const void* p) {
    uint32_t a;
    asm("{ .reg .u64 t; cvta.to.shared.u64 t, %1; cvt.u32.u64 %0, t; }" : "=r"(a) : "l"(p));
    return a;
}
__device__ __forceinline__ void cpa16(uint32_t d, const void* s) {
    asm volatile("cp.async.cg.shared.global [%0], [%1], 16;" :: "r"(d), "l"(s));
}
#define CP_COMMIT() asm volatile("cp.async.commit_group;")
#define CP_WAIT(n)  asm volatile("cp.async.wait_group %0;" :: "n"(n))

#define LDM4(r0, r1, r2, r3, a) \
    asm volatile("ldmatrix.sync.aligned.m8n8.x4.shared.b16 {%0,%1,%2,%3}, [%4];" \
                 : "=r"(r0), "=r"(r1), "=r"(r2), "=r"(r3) : "r"(a))

#define MMA16816(c, a, b) \
    asm volatile("mma.sync.aligned.m16n8k16.row.col.f32.bf16.bf16.f32 " \
                 "{%0,%1,%2,%3}, {%4,%5,%6,%7}, {%8,%9}, {%0,%1,%2,%3};" \
                 : "+f"((c)[0]), "+f"((c)[1]), "+f"((c)[2]), "+f"((c)[3]) \
                 : "r"((a)[0]), "r"((a)[1]), "r"((a)[2]), "r"((a)[3]), \
                   "r"((b)[0]), "r"((b)[1]))

__device__ __forceinline__ uint32_t pk(__nv_bfloat16 a, __nv_bfloat16 b) {
    __nv_bfloat162 t = __halves2bfloat162(a, b);
    return *reinterpret_cast<uint32_t*>(&t);
}
__device__ __forceinline__ float2 upk(uint32_t u) {
    __nv_bfloat162 t = *reinterpret_cast<__nv_bfloat162*>(&u);
    return __bfloat1622float2(t);
}
__device__ __forceinline__ void bsplit2(__nv_bfloat16* H, __nv_bfloat16* L, size_t i, float a, float b) {
    __nv_bfloat16 ha = __float2bfloat16(a), hb = __float2bfloat16(b);
    *(uint32_t*)(H + i) = pk(ha, hb);
    *(uint32_t*)(L + i) = pk(__float2bfloat16(a - __bfloat162float(ha)),
                             __float2bfloat16(b - __bfloat162float(hb)));
}
__device__ __forceinline__ void bsplit8(__nv_bfloat16* H, __nv_bfloat16* L, size_t i,
                                        float4 v0, float4 v1) {
    __nv_bfloat16 h0 = __float2bfloat16(v0.x), h1 = __float2bfloat16(v0.y),
                  h2 = __float2bfloat16(v0.z), h3 = __float2bfloat16(v0.w),
                  h4 = __float2bfloat16(v1.x), h5 = __float2bfloat16(v1.y),
                  h6 = __float2bfloat16(v1.z), h7 = __float2bfloat16(v1.w);
    *(uint4*)(H + i) = make_uint4(pk(h0, h1), pk(h2, h3), pk(h4, h5), pk(h6, h7));
    *(uint4*)(L + i) = make_uint4(
        pk(__float2bfloat16(v0.x - __bfloat162float(h0)), __float2bfloat16(v0.y - __bfloat162float(h1))),
        pk(__float2bfloat16(v0.z - __bfloat162float(h2)), __float2bfloat16(v0.w - __bfloat162float(h3))),
        pk(__float2bfloat16(v1.x - __bfloat162float(h4)), __float2bfloat16(v1.y - __bfloat162float(h5))),
        pk(__float2bfloat16(v1.z - __bfloat162float(h6)), __float2bfloat16(v1.w - __bfloat162float(h7))));
}
__device__ __forceinline__ void atomicMinF(float* addr, float val) {
    int old = __float_as_int(*addr);
    while (val < __int_as_float(old)) {
        int assumed = old;
        old = atomicCAS((int*)addr, assumed, __float_as_int(val));
        if (old == assumed) break;
    }
}
__device__ __forceinline__ void atomicMaxF(float* addr, float val) {
    int old = __float_as_int(*addr);
    while (val > __int_as_float(old)) {
        int assumed = old;
        old = atomicCAS((int*)addr, assumed, __float_as_int(val));
        if (old == assumed) break;
    }
}

__global__ void k_init() {
    g_minmax[0] = __int_as_float(0x7f800000);
    g_minmax[1] = __int_as_float(0xff800000);
}
__global__ void k_scale() {
    float mn = g_minmax[0], mx = g_minmax[1];
    g_ms[0] = mn;
    g_ms[1] = 1.0f / (mx - mn);
}

// ---------------- prep kernels (8 elems/thread, vectorized) ----------------
__global__ void k_prep_x(const float* __restrict__ xr, const float* __restrict__ xi) {
    size_t i8 = ((size_t)blockIdx.x * 256 + threadIdx.x) * 8;   // 4096*2048
    int m = (int)(i8 >> 11), k = (int)(i8 & 2047);
    const float* src = (k < 1024) ? (xr + (size_t)m * 1024 + k) : (xi + (size_t)m * 1024 + k - 1024);
    float4 v0 = *(const float4*)(src);
    float4 v1 = *(const float4*)(src + 4);
    bsplit8(g_xh, g_xl, i8, v0, v1);
}
__global__ void k_prep_w(const float* __restrict__ wr, const float* __restrict__ wi) {
    size_t i8 = ((size_t)blockIdx.x * 256 + threadIdx.x) * 8;   // 6144*2048
    int p = (int)(i8 >> 11), k = (int)(i8 & 2047);
    int n = p >> 1;
    float4 v0, v1;
    if (!(p & 1)) {
        if (k < 1024) {
            v0 = *(const float4*)(wr + (size_t)n * 1024 + k);
            v1 = *(const float4*)(wr + (size_t)n * 1024 + k + 4);
        } else {
            v0 = *(const float4*)(wi + (size_t)n * 1024 + k - 1024);
            v1 = *(const float4*)(wi + (size_t)n * 1024 + k - 1020);
            v0.x = -v0.x; v0.y = -v0.y; v0.z = -v0.z; v0.w = -v0.w;
            v1.x = -v1.x; v1.y = -v1.y; v1.z = -v1.z; v1.w = -v1.w;
        }
    } else {
        const float* src = (k < 1024) ? (wi + (size_t)n * 1024 + k) : (wr + (size_t)n * 1024 + k - 1024);
        v0 = *(const float4*)(src);
        v1 = *(const float4*)(src + 4);
    }
    bsplit8(g_wh, g_wl, i8, v0, v1);
}
__global__ void k_prep_ow(const float* __restrict__ owr, const float* __restrict__ owi) {
    size_t i8 = ((size_t)blockIdx.x * 256 + threadIdx.x) * 8;   // 2048*2048
    int p = (int)(i8 >> 11), k = (int)(i8 & 2047);
    int n = p >> 1;
    float4 v0, v1;
    if (!(p & 1)) {
        if (k < 1024) {
            v0 = *(const float4*)(owr + (size_t)n * 1024 + k);
            v1 = *(const float4*)(owr + (size_t)n * 1024 + k + 4);
        } else {
            v0 = *(const float4*)(owi + (size_t)n * 1024 + k - 1024);
            v1 = *(const float4*)(owi + (size_t)n * 1024 + k - 1020);
            v0.x = -v0.x; v0.y = -v0.y; v0.z = -v0.z; v0.w = -v0.w;
            v1.x = -v1.x; v1.y = -v1.y; v1.z = -v1.z; v1.w = -v1.w;
        }
    } else {
        const float* src = (k < 1024) ? (owi + (size_t)n * 1024 + k) : (owr + (size_t)n * 1024 + k - 1024);
        v0 = *(const float4*)(src);
        v1 = *(const float4*)(src + 4);
    }
    bsplit8(g_owh, g_owl, i8, v0, v1);
}

// ---------------- transforms ----------------
__global__ void k_trans_qk(const float* __restrict__ br, const float* __restrict__ bi) {
    int idx = blockIdx.x * 256 + threadIdx.x;   // 64*1024*32
    int hd2 = (idx & 31) * 2, t = (idx >> 5) & 1023, bh = idx >> 15;
    int b = bh >> 4, h = bh & 15;
    size_t m = (size_t)t * 4 + b;
    int nq = h * 64 + hd2;
    const float* cr = g_c1 + m * 6144;
    float4 q = *(const float4*)(cr + 2 * nq);
    float4 kv = *(const float4*)(cr + 2 * nq + 2048);
    float qr0 = q.x + br[nq],     qi0 = q.y + bi[nq];
    float qr1 = q.z + br[nq + 1], qi1 = q.w + bi[nq + 1];
    float kr0 = kv.x + br[nq + 1024], ki0 = kv.y + bi[nq + 1024];
    float kr1 = kv.z + br[nq + 1025], ki1 = kv.w + bi[nq + 1025];
    size_t base = ((size_t)bh * 1024 + t) * 128;
    bsplit2(g_qh, g_ql, base + hd2,      qr0 * SCALE_Q, qr1 * SCALE_Q);
    bsplit2(g_qh, g_ql, base + 64 + hd2, qi0 * SCALE_Q, qi1 * SCALE_Q);
    bsplit2(g_kh, g_kl, base + hd2,      kr0 + ki0, kr1 + ki1);
    bsplit2(g_kh, g_kl, base + 64 + hd2, kr0 - ki0, kr1 - ki1);
}

__global__ void k_trans_v(const float* __restrict__ br, const float* __restrict__ bi) {
    __shared__ float sv[64][129];
    int bh = blockIdx.y, tblk = blockIdx.x;
    int b = bh >> 4, h = bh & 15;
    for (int i = threadIdx.x; i < 8192; i += 256) {
        int tl = i >> 7, n = i & 127;
        int hd = n & 63;
        int im = (n >= 64);
        size_t m = (size_t)(tblk * 64 + tl) * 4 + b;
        int nv = 2048 + h * 64 + hd;
        sv[tl][n] = g_c1[m * 6144 + 2 * nv + im] + (im ? bi[nv] : br[nv]);
    }
    __syncthreads();
    for (int i = threadIdx.x; i < 4096; i += 256) {
        int n = i >> 5, tl2 = (i & 31) * 2;
        size_t o = ((size_t)bh * 128 + n) * 1024 + tblk * 64 + tl2;
        bsplit2(g_vth, g_vtl, o, sv[tl2][n], sv[tl2 + 1][n]);
    }
}

__global__ void k_vsum() {
    int bh = blockIdx.x, n = threadIdx.x;
    const __nv_bfloat16* ph = g_vth + ((size_t)bh * 128 + n) * 1024;
    const __nv_bfloat16* pl = g_vtl + ((size_t)bh * 128 + n) * 1024;
    float s = 0.f;
    for (int t = 0; t < 1024; t += 2) {
        float2 a = upk(*(const uint32_t*)(ph + t));
        float2 b = upk(*(const uint32_t*)(pl + t));
        s += a.x + a.y + b.x + b.y;
    }
    g_vsum[bh * 128 + n] = s;
}

__global__ void k_avg(float* __restrict__ out) {
    size_t i4 = ((size_t)blockIdx.x * 256 + threadIdx.x) * 4;   // 4Mi outputs
    int b = (int)(i4 >> 20);
    size_t qk = i4 & 0xFFFFFu;
    float s0 = 0.f, s1 = 0.f, s2 = 0.f, s3 = 0.f;
    #pragma unroll
    for (int h = 0; h < 16; h++) {
        size_t o = (((size_t)(b * 16 + h)) << 20) + qk;
        uint2 uh = *(const uint2*)(g_awh + o);
        uint2 ul = *(const uint2*)(g_awl + o);
        float2 a0 = upk(uh.x), a1 = upk(uh.y), b0 = upk(ul.x), b1 = upk(ul.y);
        s0 += a0.x + b0.x; s1 += a0.y + b0.y;
        s2 += a1.x + b1.x; s3 += a1.y + b1.y;
    }
    float mn = g_ms[0], sc = g_ms[1];
    float4 r;
    r.x = (s0 * 0.0625f - mn) * sc; r.y = (s1 * 0.0625f - mn) * sc;
    r.z = (s2 * 0.0625f - mn) * sc; r.w = (s3 * 0.0625f - mn) * sc;
    *(float4*)(out + i4) = r;
}

// ---------------- HMMA GEMM (bf16 3-product, 3-stage cp.async, 1 sync/iter) ----------------
// MODE 0: proj  A=g_x     B=g_w   C=g_c1               K=2048
// MODE 1: qk    A=g_q     B=g_k   C=awh/awl + minmax   K=128,  z=head
// MODE 2: av    A=awh/awl B=g_vt  C=a2h/a2l (affine)   K=1024, z=head
// MODE 3: oproj A=g_a2    B=g_ow  C=out re/im+bias     K=2048
template<int MODE>
__global__ __launch_bounds__(256, 2) void k_gemm(
    const float* __restrict__ biasR, const float* __restrict__ biasI,
    float* __restrict__ outR, float* __restrict__ outI)
{
    extern __shared__ char sm[];
    const int tid = threadIdx.x, lane = tid & 31, wid = tid >> 5;
    const int wm = wid >> 2, wn = wid & 3;
    const int bm = blockIdx.y * 128, bn = blockIdx.x * 128, z = blockIdx.z;

    constexpr int ld = (MODE == 1) ? 128 : (MODE == 2) ? 1024 : 2048;
    constexpr int nk = (MODE == 1) ? 4 : (MODE == 2) ? 32 : 64;
    constexpr int STG = 32768;

    const __nv_bfloat16 *Ah, *Al, *Bh, *Bl;
    if (MODE == 0)      { Ah = g_xh;  Al = g_xl;  Bh = g_wh;  Bl = g_wl; }
    else if (MODE == 1) {
        Ah = g_qh + (size_t)z * 131072; Al = g_ql + (size_t)z * 131072;
        Bh = g_kh + (size_t)z * 131072; Bl = g_kl + (size_t)z * 131072;
    } else if (MODE == 2) {
        Ah = g_awh + ((size_t)z << 20); Al = g_awl + ((size_t)z << 20);
        Bh = g_vth + (size_t)z * 131072; Bl = g_vtl + (size_t)z * 131072;
    } else              { Ah = g_a2h; Al = g_a2l; Bh = g_owh; Bl = g_owl; }

    const uint32_t sb = s2u(sm);
    float acc[4][4][4] = {};

    const int srow = tid >> 1, sc0 = (tid & 1) * 2;
    const int ra  = (lane & 7) + ((lane >> 3) & 1) * 8;
    const int ksa = lane >> 4;
    const int rb  = wn * 32 + ((lane >> 4) & 1) * 8 + (lane & 7);
    const int ksb = (lane >> 3) & 1;

    auto stage_fn = [&](int kts, int buf) {
        const int k0 = kts * 32;
        const __nv_bfloat16* srcs[4] = {Ah, Al, Bh, Bl};
        const int rbase[4] = {bm, bm, bn, bn};
        #pragma unroll
        for (int o = 0; o < 4; o++) {
            size_t g = (size_t)(rbase[o] + srow) * ld + k0;
            uint32_t db = sb + buf * STG + o * 8192 + srow * 64;
            #pragma unroll
            for (int u = 0; u < 2; u++) {
                int c = sc0 + u;
                cpa16(db + ((c ^ ((srow >> 1) & 3)) << 4), srcs[o] + g + c * 8);
            }
        }
        CP_COMMIT();
    };

    // prologue: stages 0 and 1 (separate commit groups)
    stage_fn(0, 0);
    stage_fn(1, 1);

    int bufc = 0;          // compute buffer = kt % 3
    int bufs = 2;          // stage buffer   = (kt+2) % 3
    for (int kt = 0; kt < nk; kt++) {
        if (kt + 1 < nk) { CP_WAIT(1); } else { CP_WAIT(0); }
        __syncthreads();
        if (kt + 2 < nk) stage_fn(kt + 2, bufs);

        // ---- compute on buffer bufc ----
        {
            const uint32_t base = sb + bufc * STG;
            #pragma unroll
            for (int kk = 0; kk < 2; kk++) {
                uint32_t bH[4][2], bL[4][2];
                #pragma unroll
                for (int jj = 0; jj < 2; jj++) {
                    int row = rb + jj * 16;
                    int seg = kk * 2 + ksb;
                    uint32_t off = row * 64 + ((seg ^ ((row >> 1) & 3)) << 4);
                    LDM4(bH[2*jj][0], bH[2*jj][1], bH[2*jj+1][0], bH[2*jj+1][1], base + 16384 + off);
                    LDM4(bL[2*jj][0], bL[2*jj][1], bL[2*jj+1][0], bL[2*jj+1][1], base + 24576 + off);
                }
                #pragma unroll
                for (int i = 0; i < 4; i++) {
                    uint32_t aH[4], aL[4];
                    int row = wm * 64 + i * 16 + ra;
                    int seg = kk * 2 + ksa;
                    uint32_t off = row * 64 + ((seg ^ ((row >> 1) & 3)) << 4);
                    LDM4(aH[0], aH[1], aH[2], aH[3], base + off);
                    LDM4(aL[0], aL[1], aL[2], aL[3], base + 8192 + off);
                    #pragma unroll
                    for (int j = 0; j < 4; j++) {
                        MMA16816(acc[i][j], aH, bH[j]);
                        MMA16816(acc[i][j], aH, bL[j]);
                        MMA16816(acc[i][j], aL, bH[j]);
                    }
                }
            }
        }
        bufc = (bufc == 2) ? 0 : bufc + 1;
        bufs = (bufs == 2) ? 0 : bufs + 1;
    }
    __syncthreads();   // protect smem reuse in MODE1 reduction

    // ---------------- epilogue ----------------
    float lmn = __int_as_float(0x7f800000), lmx = __int_as_float(0xff800000);
    float scv = 0.f, mnsc = 0.f;
    if (MODE == 2) { scv = g_ms[1]; mnsc = g_ms[0] * scv; }

    #pragma unroll
    for (int i = 0; i < 4; i++) {
        const int r0 = bm + wm * 64 + i * 16 + (lane >> 2);
        #pragma unroll
        for (int j = 0; j < 4; j++) {
            const float* c = acc[i][j];
            const int n0 = wn * 32 + j * 8 + (lane & 3) * 2;
            if (MODE == 0) {
                *(float2*)(g_c1 + (size_t)r0 * 6144 + bn + n0)       = make_float2(c[0], c[1]);
                *(float2*)(g_c1 + (size_t)(r0 + 8) * 6144 + bn + n0) = make_float2(c[2], c[3]);
            } else if (MODE == 1) {
                __nv_bfloat16* AH = g_awh + ((size_t)z << 20);
                __nv_bfloat16* AL = g_awl + ((size_t)z << 20);
                bsplit2(AH, AL, (size_t)r0 * 1024 + bn + n0, c[0], c[1]);
                bsplit2(AH, AL, (size_t)(r0 + 8) * 1024 + bn + n0, c[2], c[3]);
                lmn = fminf(lmn, fminf(fminf(c[0], c[1]), fminf(c[2], c[3])));
                lmx = fmaxf(lmx, fmaxf(fmaxf(c[0], c[1]), fmaxf(c[2], c[3])));
            } else if (MODE == 2) {
                const int b = z >> 4, h = z & 15;
                const float* S = g_vsum + z * 128;
                float v00 = scv * c[0] - mnsc * S[n0];
                float v01 = scv * c[1] - mnsc * S[n0 + 1];
                float v10 = scv * c[2] - mnsc * S[n0];
                float v11 = scv * c[3] - mnsc * S[n0 + 1];
                size_t e = (n0 < 64) ? (size_t)(h * 64 + n0) : (size_t)(1024 + h * 64 + n0 - 64);
                bsplit2(g_a2h, g_a2l, ((size_t)r0 * 4 + b) * 2048 + e, v00, v01);
                bsplit2(g_a2h, g_a2l, ((size_t)(r0 + 8) * 4 + b) * 2048 + e, v10, v11);
            } else {
                const int nc = ((bn + n0) >> 1);
                outR[(size_t)r0 * 1024 + nc]       = c[0] + biasR[nc];
                outI[(size_t)r0 * 1024 + nc]       = c[1] + biasI[nc];
                outR[(size_t)(r0 + 8) * 1024 + nc] = c[2] + biasR[nc];
                outI[(size_t)(r0 + 8) * 1024 + nc] = c[3] + biasI[nc];
            }
        }
    }
    if (MODE == 1) {
        #pragma unroll
        for (int off = 16; off; off >>= 1) {
            lmn = fminf(lmn, __shfl_xor_sync(0xffffffffu, lmn, off));
            lmx = fmaxf(lmx, __shfl_xor_sync(0xffffffffu, lmx, off));
        }
        float* red = (float*)sm;
        if (lane == 0) { red[wid] = lmn; red[8 + wid] = lmx; }
        __syncthreads();
        if (tid == 0) {
            float mn = red[0], mx = red[8];
            #pragma unroll
            for (int w = 1; w < 8; w++) { mn = fminf(mn, red[w]); mx = fmaxf(mx, red[8 + w]); }
            atomicMinF(&g_minmax[0], mn);
            atomicMaxF(&g_minmax[1], mx);
        }
    }
}

// ---------------- launch ----------------
extern "C" void kernel_launch(void* const* d_in, const int* in_sizes, int n_in,
                              void* d_out, int out_size)
{
    const float* xr  = (const float*)d_in[0];
    const float* xi  = (const float*)d_in[1];
    const float* wr  = (const float*)d_in[2];
    const float* wi  = (const float*)d_in[3];
    const float* br  = (const float*)d_in[4];
    const float* bi  = (const float*)d_in[5];
    const float* owr = (const float*)d_in[6];
    const float* owi = (const float*)d_in[7];
    const float* obr = (const float*)d_in[8];
    const float* obi = (const float*)d_in[9];
    float* out = (float*)d_out;

    const int SMEM = 98304;   // 3 stages x 32KB
    cudaFuncSetAttribute(k_gemm<0>, cudaFuncAttributeMaxDynamicSharedMemorySize, SMEM);
    cudaFuncSetAttribute(k_gemm<1>, cudaFuncAttributeMaxDynamicSharedMemorySize, SMEM);
    cudaFuncSetAttribute(k_gemm<2>, cudaFuncAttributeMaxDynamicSharedMemorySize, SMEM);
    cudaFuncSetAttribute(k_gemm<3>, cudaFuncAttributeMaxDynamicSharedMemorySize, SMEM);

    k_init<<<1, 1>>>();
    k_prep_x<<<4096, 256>>>(xr, xi);
    k_prep_w<<<6144, 256>>>(wr, wi);
    k_prep_ow<<<2048, 256>>>(owr, owi);

    k_gemm<0><<<dim3(48, 32), 256, SMEM>>>(nullptr, nullptr, nullptr, nullptr);
    k_trans_qk<<<8192, 256>>>(br, bi);
    k_trans_v<<<dim3(16, 64), 256>>>(br, bi);
    k_vsum<<<64, 128>>>();

    k_gemm<1><<<dim3(8, 8, 64), 256, SMEM>>>(nullptr, nullptr, nullptr, nullptr);
    k_scale<<<1, 1>>>();

    k_gemm<2><<<dim3(1, 8, 64), 256, SMEM>>>(nullptr, nullptr, nullptr, nullptr);
    k_avg<<<4096, 256>>>(out + 2 * (size_t)SEG);

    k_gemm<3><<<dim3(16, 32), 256, SMEM>>>(obr, obi, out, out + SEG);
}